// round 12
// baseline (speedup 1.0000x reference)
#include <cuda_runtime.h>
#include <cstdint>

// LossGenerator: T=11, H=W=2048. Inputs u=output, f1, each [11,1,2048,2048] f32.
// Output: [phy, bc] f32. Single fused kernel.
// TMA bulk pipeline (cp.async.bulk + mbarrier, 4 slots): one elected thread
// issues 18 bulk copies per time slice (10 u rows of 288B incl. halos, 8 f1
// rows of 256B); warps consume via LDS only. Compute: float2 lanes, separable
// stencil q-trick, 2 shuffles/t, uc[11][2] temporal history.

#define HH 2048
#define WI 2048
static const size_t HWs = (size_t)HH * (size_t)WI;

#define NB_BC   10
#define NB_PHY  8192     // 32 col-segments (64 px) x 256 row-groups (8 rows)
#define NB_TOT  (NB_BC + NB_PHY)

#define RSU     72                 // u smem row: 4 left pad/halo + 64 + 4 right
#define SU_ST   (10 * RSU)         // 720 floats per stage
#define SF_ST   (8 * 64)           // 512 floats per stage

__device__ double   g_phy;
__device__ double   g_bc;
__device__ unsigned g_count;

constexpr double PREFD = 3.5682482323055424;  // 0.1^{-0.5}/Gamma(1.5)
constexpr double WQ[10] = {
    1.0,
    0.41421356237309515,
    0.31783724519578215,
    0.26794919243112270,
    0.23606797749978969,
    0.21342176528338802,
    0.19626156828141264,
    0.18267581368159972,
    0.17157287525380971,
    0.16227766016837933
};

__device__ __forceinline__ void bulk_cp(uint32_t smem, const void* g,
                                        uint32_t bytes, uint32_t mbar) {
    asm volatile(
        "cp.async.bulk.shared::cta.global.mbarrier::complete_tx::bytes "
        "[%0], [%1], %2, [%3];"
        :: "r"(smem), "l"(g), "r"(bytes), "r"(mbar) : "memory");
}

__device__ __forceinline__ void mbar_init(uint32_t mbar, uint32_t count) {
    asm volatile("mbarrier.init.shared.b64 [%0], %1;" :: "r"(mbar), "r"(count)
                 : "memory");
}

__device__ __forceinline__ void mbar_expect_tx(uint32_t mbar, uint32_t bytes) {
    asm volatile("mbarrier.arrive.expect_tx.shared.b64 _, [%0], %1;"
                 :: "r"(mbar), "r"(bytes) : "memory");
}

__device__ __forceinline__ void mbar_wait(uint32_t mbar, uint32_t parity) {
    asm volatile(
        "{\n\t"
        ".reg .pred P1;\n\t"
        "WAIT_LOOP_%=:\n\t"
        "mbarrier.try_wait.parity.acquire.cta.shared::cta.b64 P1, [%0], %1, 0x989680;\n\t"
        "@P1 bra.uni WAIT_DONE_%=;\n\t"
        "bra.uni WAIT_LOOP_%=;\n\t"
        "WAIT_DONE_%=:\n\t"
        "}"
        :: "r"(mbar), "r"(parity) : "memory");
}

__device__ __forceinline__ void block_reduce_add(double v, double* target, int tid) {
    #pragma unroll
    for (int o = 16; o > 0; o >>= 1)
        v += __shfl_down_sync(0xffffffffu, v, o);
    __shared__ double sr[8];
    int lane = tid & 31, wid = tid >> 5;
    if (lane == 0) sr[wid] = v;
    __syncthreads();
    if (wid == 0) {
        v = (lane < 8) ? sr[lane] : 0.0;
        #pragma unroll
        for (int o = 4; o > 0; o >>= 1)
            v += __shfl_down_sync(0xffffffffu, v, o);
        if (lane == 0) atomicAdd(target, v);
    }
}

__global__ __launch_bounds__(256, 4) void fused_kernel(const float* __restrict__ u,
                                                       const float* __restrict__ f1,
                                                       float* __restrict__ out) {
    const int tid = threadIdx.x;
    const int bid = blockIdx.x;

    __shared__ alignas(128) float su[4 * SU_ST];          // 11520 B
    __shared__ alignas(128) float sfl[4 * SF_ST];         //  8192 B
    __shared__ alignas(8)   unsigned long long mbar[4];

    if (bid < NB_BC) {
        // ---------------- boundary-condition loss ----------------
        const int it = bid;                      // time slice it+1
        const float* ut = u + (size_t)(it + 1) * HWs;
        const float tval = 0.1f + 0.1f * (float)it;
        const float tt = powf(tval, 1.5f);

        double v = 0.0;
        #pragma unroll
        for (int jb = 0; jb < 8; jb++) {
            const int j = jb * 256 + tid;        // 0..2047
            const float xj = (float)j * (1.0f / 2047.0f);
            const float x1b = tt * sinf(6.2831853071795862f * xj);

            const float l  = ut[(size_t)j * WI];
            const float r  = ut[(size_t)j * WI + (WI - 1)];
            const float tp = ut[j];
            const float bt = ut[(size_t)(HH - 1) * WI + j];

            const float dl = l - x1b, dr = r - x1b, du = tp - x1b, db = bt - x1b;
            v += (double)(dl * dl + dr * dr + du * du + db * db);
        }
        block_reduce_add(v, &g_bc, tid);
    } else {
        // ---------------- physics residual loss ----------------
        const int b     = bid - NB_BC;
        const int lane  = tid & 31;
        const int wrp   = tid >> 5;                 // 0..7 -> output row
        const int seg   = b & 31;                   // 64-px column strip
        const int hgrp  = b >> 5;                   // 0..255
        const int h0    = 1 + hgrp * 8;             // first output row
        const int wbase = seg * 64;
        const int h     = h0 + wrp;                 // this warp's output row
        const int w0    = wbase + lane * 2;         // first of 2 pixels

        const uint32_t su_a   = (uint32_t)__cvta_generic_to_shared(su);
        const uint32_t sf_a   = (uint32_t)__cvta_generic_to_shared(sfl);
        const uint32_t mbar_a = (uint32_t)__cvta_generic_to_shared(mbar);

        // Per-block bulk-copy geometry. smem u row index = (w - wbase) + 4.
        // interior: copy 288B from gmem col wbase-4 -> smem idx0 (covers idx0..71)
        // seg 0  : copy 272B from gmem col 0       -> smem idx4 (covers idx4..71)
        // seg 31 : copy 272B from gmem col wbase-4 -> smem idx0 (covers idx0..67)
        const bool e0  = (seg == 0), e31 = (seg == 31);
        const int      gcol        = e0 ? 0 : (wbase - 4);
        const uint32_t sdst        = e0 ? 16u : 0u;
        const uint32_t ulen        = (e0 || e31) ? 272u : 288u;
        const uint32_t stage_bytes = 10u * ulen + 8u * 256u;

        // Zero-fill the smem words no bulk copy touches (edge blocks only) so
        // masked outputs stay finite (NaN*0 hazard).
        if (e0 || e31) {
            const int basei = e0 ? 0 : 68;
            for (int i = tid; i < 160; i += 256) {
                const int stg = i / 40, rem = i % 40;
                su[stg * SU_ST + (rem >> 2) * RSU + basei + (rem & 3)] = 0.0f;
            }
        }
        if (tid == 0) {
            #pragma unroll
            for (int s = 0; s < 4; s++) mbar_init(mbar_a + 8 * s, 1);
        }
        __syncthreads();

        #define ISSUE_STAGE(T, ST)                                                  \
        do {                                                                        \
            const uint32_t mb_ = mbar_a + (uint32_t)(ST) * 8u;                      \
            mbar_expect_tx(mb_, stage_bytes);                                       \
            _Pragma("unroll")                                                       \
            for (int r_ = 0; r_ < 10; r_++) {                                       \
                int hr_ = h0 - 1 + r_; if (hr_ > HH - 1) hr_ = HH - 1;              \
                bulk_cp(su_a + (uint32_t)(((ST) * SU_ST + r_ * RSU) * 4) + sdst,    \
                        u + (size_t)(T) * HWs + (size_t)hr_ * WI + gcol,            \
                        ulen, mb_);                                                 \
            }                                                                       \
            _Pragma("unroll")                                                       \
            for (int r_ = 0; r_ < 8; r_++) {                                        \
                int hr_ = h0 + r_; if (hr_ > HH - 1) hr_ = HH - 1;                  \
                bulk_cp(sf_a + (uint32_t)(((ST) * SF_ST + r_ * 64) * 4),            \
                        f1 + (size_t)(T) * HWs + (size_t)hr_ * WI + wbase,          \
                        256u, mb_);                                                 \
            }                                                                       \
        } while (0)

        if (tid == 0) {
            ISSUE_STAGE(0, 0);
            ISSUE_STAGE(1, 1);
            ISSUE_STAGE(2, 2);
        }

        const float A = 0.34520446044393f;
        const float B = 0.309591078922457f;
        const float C = -2.619182157203629f;
        const float KLAP = 0.01f * 4194304.0f;     // kappa / DX^2

        const float fPW[10] = {
            (float)(PREFD * WQ[0]), (float)(PREFD * WQ[1]), (float)(PREFD * WQ[2]),
            (float)(PREFD * WQ[3]), (float)(PREFD * WQ[4]), (float)(PREFD * WQ[5]),
            (float)(PREFD * WQ[6]), (float)(PREFD * WQ[7]), (float)(PREFD * WQ[8]),
            (float)(PREFD * WQ[9])
        };
        const float fPD[10] = {
            0.0f,
            (float)(PREFD * (WQ[0] - WQ[1])), (float)(PREFD * (WQ[1] - WQ[2])),
            (float)(PREFD * (WQ[2] - WQ[3])), (float)(PREFD * (WQ[3] - WQ[4])),
            (float)(PREFD * (WQ[4] - WQ[5])), (float)(PREFD * (WQ[5] - WQ[6])),
            (float)(PREFD * (WQ[6] - WQ[7])), (float)(PREFD * (WQ[7] - WQ[8])),
            (float)(PREFD * (WQ[8] - WQ[9]))
        };
        const float PREFF = (float)PREFD;

        const float mskA = (h <= HH - 2) ? 1.0f : 0.0f;
        const float msk0 = mskA * ((w0 == 0)      ? 0.0f : 1.0f);
        const float msk1 = mskA * ((w0 == WI - 2) ? 0.0f : 1.0f);

        float acc = 0.0f;
        float ucm[11][2];

        #pragma unroll
        for (int t = 0; t < 11; t++) {
            const int st = t & 3;

            if (t > 0) __syncthreads();              // slot (t+3)&3 now free
            if (tid == 0 && t + 3 <= 10) ISSUE_STAGE(t + 3, (t + 3) & 3);

            mbar_wait(mbar_a + (uint32_t)st * 8u, (uint32_t)((t >> 2) & 1));

            const float* rowT = su + st * SU_ST + wrp * RSU;      // u row h-1
            const float* rowM = rowT + RSU;                       // u row h
            const float* rowB = rowM + RSU;                       // u row h+1

            const float2 a2 = *(const float2*)(rowT + 4 + 2 * lane);
            const float2 m2 = *(const float2*)(rowM + 4 + 2 * lane);
            const float2 b2 = *(const float2*)(rowB + 4 + 2 * lane);
            const float2 f2 = *(const float2*)(sfl + st * SF_ST + wrp * 64 + 2 * lane);

            float qE = 0.0f;
            if (lane == 0 || lane == 31) {
                const int hi = (lane == 0) ? 3 : 68;
                qE = fmaf(A, rowT[hi] + rowB[hi], B * rowM[hi]);
            }

            const float ca0 = a2.x + b2.x, ca1 = a2.y + b2.y;
            const float q0 = fmaf(A, ca0, B * m2.x);
            const float q1 = fmaf(A, ca1, B * m2.y);

            float qL = __shfl_up_sync(0xffffffffu, q1, 1);
            float qR = __shfl_down_sync(0xffffffffu, q0, 1);
            if (lane == 0)  qL = qE;
            if (lane == 31) qR = qE;

            const float qa[4] = { qL, q0, q1, qR };
            const float ca[2] = { ca0, ca1 };
            const float mc[2] = { m2.x, m2.y };
            const float ff[2] = { f2.x, f2.y };
            const float msk[2] = { msk0, msk1 };

            #pragma unroll
            for (int j = 0; j < 2; j++) {
                const float center = mc[j];
                const float conv = qa[j] + qa[j + 2]
                                 + fmaf(B, ca[j], C * center);
                float fu = center - ff[j] - KLAP * conv;
                if (t > 0) {
                    float Dv = PREFF * center - fPW[t - 1] * ucm[0][j];
                    #pragma unroll
                    for (int k = 1; k < t; k++)
                        Dv -= fPD[t - k] * ucm[k][j];
                    fu += Dv;
                }
                fu *= msk[j];
                acc = fmaf(fu, fu, acc);
                ucm[t][j] = center;
            }
        }
        #undef ISSUE_STAGE

        block_reduce_add((double)acc, &g_phy, tid);
    }

    // ---------------- last-block finalize + reset ----------------
    if (tid == 0) {
        __threadfence();
        unsigned prev = atomicAdd(&g_count, 1u);
        if (prev == NB_TOT - 1) {
            out[0] = (float)(2.0 * g_phy / 46047276.0);   // 11*2046*2046
            out[1] = (float)(g_bc / 41943040.0);          // 10*2048*2048
            g_phy = 0.0;
            g_bc  = 0.0;
            g_count = 0u;
            __threadfence();
        }
    }
}

extern "C" void kernel_launch(void* const* d_in, const int* in_sizes, int n_in,
                              void* d_out, int out_size) {
    const float* u  = (const float*)d_in[0];
    const float* f1 = (const float*)d_in[1];
    float* out = (float*)d_out;

    fused_kernel<<<NB_TOT, 256>>>(u, f1, out);
}

// round 14
// speedup vs baseline: 1.8853x; 1.8853x over previous
#include <cuda_runtime.h>
#include <cstdint>

// LossGenerator: T=11, H=W=2048. Inputs u=output, f1, each [11,1,2048,2048] f32.
// Output: [phy, bc] f32. Single fused kernel.
// R10 staging (cp.async 4-slot pipeline for u 10 rows + halo and f1 8 rows).
// R14: correct single barrier per t: wait_group 2 (own slice-t copies done)
// -> __syncthreads (collective visibility + compute(t-1) done) -> issue(t+3)
// into slot (t-1)&3 -> compute(t).  Plus __launch_bounds__(256,5) for
// 5 CTAs/SM (48-reg cap).

#define HH 2048
#define WI 2048
static const size_t HWs = (size_t)HH * (size_t)WI;

#define NB_BC   10
#define NB_PHY  8192     // 32 col-segments (64 px) x 256 row-groups (8 rows)
#define NB_TOT  (NB_BC + NB_PHY)

#define RS      68       // smem row stride (floats): 64 main + 2 halo + 2 pad
#define SU_ROW  10
#define SF_ROW  8
#define SU_ST   (SU_ROW * RS)   // 680
#define SF_ST   (SF_ROW * RS)   // 544

__device__ double   g_phy;
__device__ double   g_bc;
__device__ unsigned g_count;

constexpr double PREFD = 3.5682482323055424;  // 0.1^{-0.5}/Gamma(1.5)
constexpr double WQ[10] = {
    1.0,
    0.41421356237309515,
    0.31783724519578215,
    0.26794919243112270,
    0.23606797749978969,
    0.21342176528338802,
    0.19626156828141264,
    0.18267581368159972,
    0.17157287525380971,
    0.16227766016837933
};

__device__ __forceinline__ void cp16(uint32_t s, const void* g) {
    asm volatile("cp.async.ca.shared.global [%0], [%1], 16;" :: "r"(s), "l"(g));
}
__device__ __forceinline__ void cp4(uint32_t s, const void* g) {
    asm volatile("cp.async.ca.shared.global [%0], [%1], 4;" :: "r"(s), "l"(g));
}
#define CP_COMMIT() asm volatile("cp.async.commit_group;" ::: "memory")
#define CP_WAIT2()  asm volatile("cp.async.wait_group 2;" ::: "memory")

__device__ __forceinline__ void block_reduce_add(double v, double* target, int tid) {
    #pragma unroll
    for (int o = 16; o > 0; o >>= 1)
        v += __shfl_down_sync(0xffffffffu, v, o);
    __shared__ double sr[8];
    int lane = tid & 31, wid = tid >> 5;
    if (lane == 0) sr[wid] = v;
    __syncthreads();
    if (wid == 0) {
        v = (lane < 8) ? sr[lane] : 0.0;
        #pragma unroll
        for (int o = 4; o > 0; o >>= 1)
            v += __shfl_down_sync(0xffffffffu, v, o);
        if (lane == 0) atomicAdd(target, v);
    }
}

__global__ __launch_bounds__(256, 5) void fused_kernel(const float* __restrict__ u,
                                                       const float* __restrict__ f1,
                                                       float* __restrict__ out) {
    const int tid = threadIdx.x;
    const int bid = blockIdx.x;

    __shared__ float su[4 * SU_ST];   // 10880 B
    __shared__ float sf[4 * SF_ST];   //  8704 B

    if (bid < NB_BC) {
        // ---------------- boundary-condition loss ----------------
        const int it = bid;                      // time slice it+1
        const float* ut = u + (size_t)(it + 1) * HWs;
        const float tval = 0.1f + 0.1f * (float)it;
        const float tt = powf(tval, 1.5f);

        double v = 0.0;
        #pragma unroll
        for (int jb = 0; jb < 8; jb++) {
            const int j = jb * 256 + tid;        // 0..2047
            const float xj = (float)j * (1.0f / 2047.0f);
            const float x1b = tt * sinf(6.2831853071795862f * xj);

            const float l  = ut[(size_t)j * WI];
            const float r  = ut[(size_t)j * WI + (WI - 1)];
            const float tp = ut[j];
            const float bt = ut[(size_t)(HH - 1) * WI + j];

            const float dl = l - x1b, dr = r - x1b, du = tp - x1b, db = bt - x1b;
            v += (double)(dl * dl + dr * dr + du * du + db * db);
        }
        block_reduce_add(v, &g_bc, tid);
    } else {
        // ---------------- physics residual loss ----------------
        const int b     = bid - NB_BC;
        const int lane  = tid & 31;
        const int wrp   = tid >> 5;                 // 0..7 -> output row
        const int seg   = b & 31;                   // 64-px column strip
        const int hgrp  = b >> 5;                   // 0..255
        const int h0    = 1 + hgrp * 8;             // first output row
        const int wbase = seg * 64;
        const int h     = h0 + wrp;                 // this warp's output row
        const int w0    = wbase + lane * 2;         // first of 2 pixels

        const uint32_t su_base = (uint32_t)__cvta_generic_to_shared(su);
        const uint32_t sf_base = (uint32_t)__cvta_generic_to_shared(sf);

        // ---- loader assignment (fixed across t) ----
        // u tile: 10 rows x 16 chunks = 160 cp16 items -> tids 0..159.
        // f tile:  8 rows x 16 chunks = 128 cp16 items -> tids 160..255 take
        //          items 0..95, tids 0..31 take items 96..127 (second copy).
        // halo:   10 rows x 2 sides   =  20 cp4  items -> tids 0..19.
        const bool ldu = (tid < 160);
        size_t gu_off = 0; uint32_t su_off = 0;
        if (ldu) {
            const int ur = tid >> 4, c = tid & 15;
            int hr = h0 - 1 + ur; if (hr > HH - 1) hr = HH - 1;
            gu_off = (size_t)hr * WI + wbase + 4 * c;
            su_off = su_base + (uint32_t)((ur * RS + 4 * c) * 4);
        }
        const int  fitem = (tid >= 160) ? (tid - 160) : (tid < 32 ? 96 + tid : -1);
        const bool ldf = (fitem >= 0);
        size_t gf_off = 0; uint32_t sf_off = 0;
        if (ldf) {
            const int fr = fitem >> 4, c = fitem & 15;
            int hr = h0 + fr; if (hr > HH - 1) hr = HH - 1;
            gf_off = (size_t)hr * WI + wbase + 4 * c;
            sf_off = sf_base + (uint32_t)((fr * RS + 4 * c) * 4);
        }
        const bool ldh = (tid < 20);
        size_t gh_off = 0; uint32_t sh_off = 0;
        if (ldh) {
            const int hrr = tid >> 1, hside = tid & 1;
            int hr = h0 - 1 + hrr; if (hr > HH - 1) hr = HH - 1;
            int col = hside ? (wbase + 64 > WI - 1 ? WI - 1 : wbase + 64)
                            : (wbase - 1 < 0 ? 0 : wbase - 1);
            gh_off = (size_t)hr * WI + col;
            sh_off = su_base + (uint32_t)((hrr * RS + 64 + hside) * 4);
        }

        #define LOAD_STAGE(T, ST)                                                   \
        do {                                                                        \
            if (ldu)                                                                \
                cp16(su_off + (uint32_t)((ST) * SU_ST * 4),                         \
                     u + (size_t)(T) * HWs + gu_off);                               \
            if (ldf)                                                                \
                cp16(sf_off + (uint32_t)((ST) * SF_ST * 4),                         \
                     f1 + (size_t)(T) * HWs + gf_off);                              \
            if (ldh)                                                                \
                cp4(sh_off + (uint32_t)((ST) * SU_ST * 4),                          \
                    u + (size_t)(T) * HWs + gh_off);                                \
            CP_COMMIT();                                                            \
        } while (0)

        LOAD_STAGE(0, 0);
        LOAD_STAGE(1, 1);
        LOAD_STAGE(2, 2);

        const float A = 0.34520446044393f;
        const float B = 0.309591078922457f;
        const float C = -2.619182157203629f;
        const float KLAP = 0.01f * 4194304.0f;     // kappa / DX^2

        const float fPW[10] = {
            (float)(PREFD * WQ[0]), (float)(PREFD * WQ[1]), (float)(PREFD * WQ[2]),
            (float)(PREFD * WQ[3]), (float)(PREFD * WQ[4]), (float)(PREFD * WQ[5]),
            (float)(PREFD * WQ[6]), (float)(PREFD * WQ[7]), (float)(PREFD * WQ[8]),
            (float)(PREFD * WQ[9])
        };
        const float fPD[10] = {
            0.0f,
            (float)(PREFD * (WQ[0] - WQ[1])), (float)(PREFD * (WQ[1] - WQ[2])),
            (float)(PREFD * (WQ[2] - WQ[3])), (float)(PREFD * (WQ[3] - WQ[4])),
            (float)(PREFD * (WQ[4] - WQ[5])), (float)(PREFD * (WQ[5] - WQ[6])),
            (float)(PREFD * (WQ[6] - WQ[7])), (float)(PREFD * (WQ[7] - WQ[8])),
            (float)(PREFD * (WQ[8] - WQ[9]))
        };
        const float PREFF = (float)PREFD;

        const float mskA = (h <= HH - 2) ? 1.0f : 0.0f;
        const float msk0 = mskA * ((w0 == 0)      ? 0.0f : 1.0f);
        const float msk1 = mskA * ((w0 == WI - 2) ? 0.0f : 1.0f);

        float acc = 0.0f;
        float ucm[11][2];

        #pragma unroll
        for (int t = 0; t < 11; t++) {
            const int st = t & 3;

            // Wait for own slice-t copies (3 groups pending -> oldest done),
            // then one barrier: makes ALL threads' slice-t data visible AND
            // proves compute(t-1) finished, so slot (t+3)&3 == (t-1)&3 is free.
            CP_WAIT2();
            __syncthreads();
            if (t + 3 <= 10) { LOAD_STAGE(t + 3, (t + 3) & 3); }
            else             { CP_COMMIT(); }

            const float* rowT = su + st * SU_ST + wrp * RS;   // u row h-1
            const float* rowM = rowT + RS;                    // u row h
            const float* rowB = rowM + RS;                    // u row h+1
            const float* rowF = sf + st * SF_ST + wrp * RS;   // f1 row h

            const float2 a2 = *(const float2*)(rowT + 2 * lane);
            const float2 m2 = *(const float2*)(rowM + 2 * lane);
            const float2 b2 = *(const float2*)(rowB + 2 * lane);
            const float2 f2 = *(const float2*)(rowF + 2 * lane);

            float qE = 0.0f;
            if (lane == 0 || lane == 31) {
                const int hi = (lane == 0) ? 64 : 65;
                qE = fmaf(A, rowT[hi] + rowB[hi], B * rowM[hi]);
            }

            const float ca0 = a2.x + b2.x, ca1 = a2.y + b2.y;
            const float q0 = fmaf(A, ca0, B * m2.x);
            const float q1 = fmaf(A, ca1, B * m2.y);

            float qL = __shfl_up_sync(0xffffffffu, q1, 1);
            float qR = __shfl_down_sync(0xffffffffu, q0, 1);
            if (lane == 0)  qL = qE;
            if (lane == 31) qR = qE;

            const float qa[4] = { qL, q0, q1, qR };
            const float ca[2] = { ca0, ca1 };
            const float mc[2] = { m2.x, m2.y };
            const float ff[2] = { f2.x, f2.y };
            const float msk[2] = { msk0, msk1 };

            #pragma unroll
            for (int j = 0; j < 2; j++) {
                const float center = mc[j];
                const float conv = qa[j] + qa[j + 2]
                                 + fmaf(B, ca[j], C * center);
                float fu = center - ff[j] - KLAP * conv;
                if (t > 0) {
                    float Dv = PREFF * center - fPW[t - 1] * ucm[0][j];
                    #pragma unroll
                    for (int k = 1; k < t; k++)
                        Dv -= fPD[t - k] * ucm[k][j];
                    fu += Dv;
                }
                fu *= msk[j];
                acc = fmaf(fu, fu, acc);
                ucm[t][j] = center;
            }
        }

        block_reduce_add((double)acc, &g_phy, tid);
        #undef LOAD_STAGE
    }

    // ---------------- last-block finalize + reset ----------------
    if (tid == 0) {
        __threadfence();
        unsigned prev = atomicAdd(&g_count, 1u);
        if (prev == NB_TOT - 1) {
            out[0] = (float)(2.0 * g_phy / 46047276.0);   // 11*2046*2046
            out[1] = (float)(g_bc / 41943040.0);          // 10*2048*2048
            g_phy = 0.0;
            g_bc  = 0.0;
            g_count = 0u;
            __threadfence();
        }
    }
}

extern "C" void kernel_launch(void* const* d_in, const int* in_sizes, int n_in,
                              void* d_out, int out_size) {
    const float* u  = (const float*)d_in[0];
    const float* f1 = (const float*)d_in[1];
    float* out = (float*)d_out;

    fused_kernel<<<NB_TOT, 256>>>(u, f1, out);
}